// round 13
// baseline (speedup 1.0000x reference)
#include <cuda_runtime.h>
#include <cuda_fp16.h>
#include <math.h>

#define BB 4096          // batch
#define CC 32000         // classes
#define NV4 8000         // float4 per row
#define NT 1024          // threads in main kernel
#define NPF 6            // chunks prefetched via cp.async (96 KB)
#define MAXGRID 160
#define NCALB 125        // MDCA blocks (32000/256)
#define NCRLB 4          // CRL blocks (4096/1024)

// Static device scratch (zero-init at load; ticket self-resets)
__device__ float g_partial[(size_t)MAXGRID * CC]; // per-block (colsum(p) - count)
__device__ float g_conf[BB];                      // per-row max softmax prob
__device__ float g_cls_arr[MAXGRID];              // per-block CE partials
__device__ float g_cal_arr[NCALB];                // per-block MDCA partials
__device__ float g_crl_arr[NCRLB];                // per-block CRL partials
__device__ unsigned g_ticket;                     // k2 last-block ticket

__device__ __forceinline__ float warp_max(float v) {
#pragma unroll
    for (int o = 16; o > 0; o >>= 1) v = fmaxf(v, __shfl_xor_sync(0xffffffffu, v, o));
    return v;
}
__device__ __forceinline__ float warp_sum(float v) {
#pragma unroll
    for (int o = 16; o > 0; o >>= 1) v += __shfl_xor_sync(0xffffffffu, v, o);
    return v;
}
__device__ __forceinline__ void cp16(float4* s, const float4* g) {
    unsigned sa = (unsigned)__cvta_generic_to_shared(s);
    asm volatile("cp.async.cg.shared.global [%0], [%1], 16;" :: "r"(sa), "l"(g));
}
#define CP_COMMIT() asm volatile("cp.async.commit_group;")
#define CP_WAIT5()  asm volatile("cp.async.wait_group 5;" ::: "memory")

// pack 4 floats -> uint2 of half2s; unpack back
__device__ __forceinline__ uint2 pack_h4(float4 e) {
    __half2 a = __floats2half2_rn(e.x, e.y);
    __half2 b = __floats2half2_rn(e.z, e.w);
    uint2 r;
    r.x = *reinterpret_cast<unsigned*>(&a);
    r.y = *reinterpret_cast<unsigned*>(&b);
    return r;
}
__device__ __forceinline__ float4 unpack_h4(uint2 h) {
    __half2 a = *reinterpret_cast<__half2*>(&h.x);
    __half2 b = *reinterpret_cast<__half2*>(&h.y);
    float2 f0 = __half22float2(a);
    float2 f1 = __half22float2(b);
    return make_float4(f0.x, f0.y, f1.x, f1.y);
}

// ---------------------------------------------------------------------------
// k1: persistent blocks. bufP (fp32, 6 chunks) recycled in-flight via
// cp.async with 1 commit group per chunk. bufE holds row r-1 exps in HALF
// precision (deferred normalize) -> smem traffic 320B/thread/row < DRAM
// fair-share, making DRAM the sole binder.
// ---------------------------------------------------------------------------
__global__ __launch_bounds__(NT, 1) void k1_main(const float* __restrict__ logits,
                                                 const int* __restrict__ targets,
                                                 int ngrid) {
    extern __shared__ float4 smem[];
    float4* bufP = smem;                                   // 6144 float4 = 96 KB
    uint2*  bufE = reinterpret_cast<uint2*>(smem + NPF * NT); // 8000 uint2 = 62.5 KB
    __shared__ float redm[32], redz[32];
    __shared__ float s_z, s_lt;

    const int tid  = threadIdx.x;
    const int lane = tid & 31;
    const int wid  = tid >> 5;
    const bool has7 = (tid + 7 * NT) < NV4;   // k=7 partial (tid < 832)

    float4 acc[8];
#pragma unroll
    for (int k = 0; k < 8; k++) acc[k] = make_float4(0.f, 0.f, 0.f, 0.f);

    // zero own bufE slots (first-row acc uses invZp=0; avoid NaN*0 from stale smem)
#pragma unroll
    for (int k = 0; k < 7; k++) bufE[tid + k * NT] = make_uint2(0u, 0u);
    if (has7) bufE[tid + 7 * NT] = make_uint2(0u, 0u);

    // prologue: prefetch first row, one commit group per chunk (NPF groups)
    const float4* r0 = reinterpret_cast<const float4*>(logits + (size_t)blockIdx.x * CC);
#pragma unroll
    for (int k = 0; k < NPF; k++) {
        cp16(bufP + tid + k * NT, r0 + tid + k * NT);
        CP_COMMIT();
    }
    float4 v6 = __ldcs(r0 + tid + 6 * NT);
    float4 v7 = has7 ? __ldcs(r0 + tid + 7 * NT) : make_float4(0.f, 0.f, 0.f, 0.f);

    float local_cls = 0.0f;
    float invZp = 0.0f;

    for (int row = blockIdx.x; row < BB; row += ngrid) {
        const int next = row + ngrid;
        const bool hasNext = next < BB;
        const float4* rn = reinterpret_cast<const float4*>(logits + (size_t)next * CC);
        const int tgt  = __ldg(targets + row);
        const int tgt4 = tgt >> 2, tgtc = tgt & 3;

        float m_t = -1e30f;
        float z_t = 0.0f;

#pragma unroll
        for (int k = 0; k < NPF; k++) {
            const int j = tid + k * NT;
            CP_WAIT5();                       // group for this chunk retired
            float4 v = bufP[j];
            if (hasNext) cp16(bufP + j, rn + j);   // recycle slot immediately
            CP_COMMIT();                      // unconditional: uniform group count
            float4 eo = unpack_h4(bufE[j]);
            acc[k].x = fmaf(eo.x, invZp, acc[k].x);
            acc[k].y = fmaf(eo.y, invZp, acc[k].y);
            acc[k].z = fmaf(eo.z, invZp, acc[k].z);
            acc[k].w = fmaf(eo.w, invZp, acc[k].w);
            float4 e;
            e.x = __expf(v.x); e.y = __expf(v.y);
            e.z = __expf(v.z); e.w = __expf(v.w);
            bufE[j] = pack_h4(e);
            m_t = fmaxf(m_t, fmaxf(fmaxf(v.x, v.y), fmaxf(v.z, v.w)));
            z_t += (e.x + e.y) + (e.z + e.w);
            if (j == tgt4) {
                s_lt = (tgtc == 0) ? v.x : ((tgtc == 1) ? v.y : ((tgtc == 2) ? v.z : v.w));
                if (tgtc == 0) acc[k].x -= 1.0f;
                else if (tgtc == 1) acc[k].y -= 1.0f;
                else if (tgtc == 2) acc[k].z -= 1.0f;
                else acc[k].w -= 1.0f;
            }
        }
        // chunks 6, 7 from registers
#pragma unroll
        for (int k = 6; k < 8; k++) {
            if (k == 7 && !has7) break;
            const int j = tid + k * NT;
            float4 v = (k == 6) ? v6 : v7;
            float4 eo = unpack_h4(bufE[j]);
            acc[k].x = fmaf(eo.x, invZp, acc[k].x);
            acc[k].y = fmaf(eo.y, invZp, acc[k].y);
            acc[k].z = fmaf(eo.z, invZp, acc[k].z);
            acc[k].w = fmaf(eo.w, invZp, acc[k].w);
            float4 e;
            e.x = __expf(v.x); e.y = __expf(v.y);
            e.z = __expf(v.z); e.w = __expf(v.w);
            bufE[j] = pack_h4(e);
            m_t = fmaxf(m_t, fmaxf(fmaxf(v.x, v.y), fmaxf(v.z, v.w)));
            z_t += (e.x + e.y) + (e.z + e.w);
            if (j == tgt4) {
                s_lt = (tgtc == 0) ? v.x : ((tgtc == 1) ? v.y : ((tgtc == 2) ? v.z : v.w));
                if (tgtc == 0) acc[k].x -= 1.0f;
                else if (tgtc == 1) acc[k].y -= 1.0f;
                else if (tgtc == 2) acc[k].z -= 1.0f;
                else acc[k].w -= 1.0f;
            }
        }
        // next-row register chunks: stream under the reduce
        if (hasNext) {
            v6 = __ldcs(rn + tid + 6 * NT);
            if (has7) v7 = __ldcs(rn + tid + 7 * NT);
        }

        // joint (max, sum) block reduce; scalar epilogue in the barrier window
        float m = warp_max(m_t);
        float z = warp_sum(z_t);
        if (lane == 0) { redm[wid] = m; redz[wid] = z; }
        __syncthreads();
        if (wid == 0) {
            m = warp_max(redm[lane]);
            z = warp_sum(redz[lane]);
            if (lane == 0) {
                s_z = z;
                float iz = 1.0f / z;
                g_conf[row] = __expf(m) * iz;     // max softmax prob
                local_cls += (logf(z) - s_lt);    // -log p[target], s_lt safe here
            }
        }
        __syncthreads();
        invZp = 1.0f / s_z;
    }

    // epilogue: pass-3 for the last processed row
#pragma unroll
    for (int k = 0; k < 8; k++) {
        if (k == 7 && !has7) break;
        float4 e = unpack_h4(bufE[tid + k * NT]);
        acc[k].x = fmaf(e.x, invZp, acc[k].x);
        acc[k].y = fmaf(e.y, invZp, acc[k].y);
        acc[k].z = fmaf(e.z, invZp, acc[k].z);
        acc[k].w = fmaf(e.w, invZp, acc[k].w);
    }

    // flush per-block column partials (coalesced float4 stores; stay in L2 for k2)
    float4* pp = reinterpret_cast<float4*>(g_partial) + (size_t)blockIdx.x * NV4;
#pragma unroll
    for (int k = 0; k < 7; k++) pp[tid + k * NT] = acc[k];
    if (has7) pp[tid + 7 * NT] = acc[7];
    if (tid == 0) g_cls_arr[blockIdx.x] = local_cls;
}

// ---------------------------------------------------------------------------
// k2: blocks 0..124 -> MDCA column reduce; blocks 125..128 -> CRL ranking.
// Last block (ticket) also does the final combine (fused former k3).
// ---------------------------------------------------------------------------
__global__ void k2_reduce(int ngrid, const int* __restrict__ idx,
                          const float* __restrict__ corr,
                          float* __restrict__ out) {
    __shared__ float red[32];
    __shared__ int s_last;
    const int tid = threadIdx.x, lane = tid & 31, wid = tid >> 5;
    const int bid = blockIdx.x;
    float s = 0.0f;

    if (bid < NCALB) {
        int c = bid * 256 + tid;
        float cs = 0.0f;
        for (int b = 0; b < ngrid; b++) cs += g_partial[(size_t)b * CC + c];
        s = fabsf(cs);                            // |colsum(p) - count|
    } else {
        int base = (bid - NCALB) * 1024;
        for (int t = tid; t < 1024; t += 256) {
            int b  = base + t;
            int b2 = (b + 1) & (BB - 1);
            float conf1 = g_conf[b];
            float conf2 = g_conf[b2];
            float c1 = __ldg(corr + __ldg(idx + b));
            float c2 = __ldg(corr + __ldg(idx + b2));
            float d  = c1 - c2;
            float rt = (d > 0.f) ? 1.f : ((d < 0.f) ? -1.f : 0.f);
            float tnz = (rt == 0.f) ? 1.f : rt;
            float ri2 = conf2 + fabsf(d) * tnz;   // margin/tnz == margin*tnz
            s += fmaxf(0.f, -rt * (conf1 - ri2));
        }
    }

    s = warp_sum(s);
    if (lane == 0) red[wid] = s;
    __syncthreads();
    if (tid == 0) {
        s = 0.0f;
#pragma unroll
        for (int w = 0; w < 8; w++) s += red[w];
        if (bid < NCALB) g_cal_arr[bid] = s;
        else             g_crl_arr[bid - NCALB] = s;
        __threadfence();
        unsigned t = atomicAdd(&g_ticket, 1u);
        s_last = (t == (unsigned)(NCALB + NCRLB - 1));
        if (s_last) g_ticket = 0;                 // self-reset for graph replay
    }
    __syncthreads();

    if (s_last) {
        __threadfence();                          // acquire published partials
        float cal = 0.f, cls = 0.f, crl = 0.f;
        for (int i = tid; i < NCALB; i += 256) cal += g_cal_arr[i];
        for (int i = tid; i < ngrid; i += 256) cls += g_cls_arr[i];
        if (tid < NCRLB) crl = g_crl_arr[tid];
        float tot = cls * (1.0f / BB) + crl * (1.0f / BB)
                  + cal * (1.0f / ((float)BB * (float)CC));
        tot = warp_sum(tot);
        if (lane == 0) red[wid] = tot;
        __syncthreads();
        if (wid == 0) {
            tot = (lane < 8) ? red[lane] : 0.0f;
            tot = warp_sum(tot);
            if (lane == 0) out[0] = tot;
        }
    }
}

extern "C" void kernel_launch(void* const* d_in, const int* in_sizes, int n_in,
                              void* d_out, int out_size) {
    const float* logits  = (const float*)d_in[0];
    const int*   targets = (const int*)d_in[1];
    const int*   idx     = (const int*)d_in[2];
    const float* corr    = (const float*)d_in[3];
    float* out = (float*)d_out;

    int sm = 148;
    cudaDeviceGetAttribute(&sm, cudaDevAttrMultiProcessorCount, 0);
    int ngrid = sm < MAXGRID ? sm : MAXGRID;

    const int smem_bytes = NPF * NT * (int)sizeof(float4)   // bufP 98304
                         + NV4 * (int)sizeof(uint2);        // bufE 64000
    cudaFuncSetAttribute(k1_main, cudaFuncAttributeMaxDynamicSharedMemorySize,
                         smem_bytes);

    k1_main<<<ngrid, NT, smem_bytes>>>(logits, targets, ngrid);
    k2_reduce<<<NCALB + NCRLB, 256>>>(ngrid, idx, corr, out);
}

// round 14
// speedup vs baseline: 1.0066x; 1.0066x over previous
#include <cuda_runtime.h>
#include <cuda_fp16.h>
#include <math.h>

#define BB 4096          // batch
#define CC 32000         // classes
#define NV4 8000         // float4 per row
#define NT 1024          // threads in main kernel
#define NPF 6            // chunks prefetched via cp.async (96 KB)
#define MAXGRID 160
#define NCALB 125        // MDCA blocks (32000/256)
#define NCRLB 4          // CRL blocks (4096/1024)

// Static device scratch (zero-init at load; ticket self-resets)
__device__ float g_partial[(size_t)MAXGRID * CC]; // per-block (colsum(p) - count)
__device__ float g_conf[BB];                      // per-row max softmax prob
__device__ float g_cls_arr[MAXGRID];              // per-block CE partials
__device__ float g_cal_arr[NCALB];                // per-block MDCA partials
__device__ float g_crl_arr[NCRLB];                // per-block CRL partials
__device__ unsigned g_ticket;                     // k2 last-block ticket

__device__ __forceinline__ float warp_max(float v) {
#pragma unroll
    for (int o = 16; o > 0; o >>= 1) v = fmaxf(v, __shfl_xor_sync(0xffffffffu, v, o));
    return v;
}
__device__ __forceinline__ float warp_sum(float v) {
#pragma unroll
    for (int o = 16; o > 0; o >>= 1) v += __shfl_xor_sync(0xffffffffu, v, o);
    return v;
}
__device__ __forceinline__ void cp16(float4* s, const float4* g) {
    unsigned sa = (unsigned)__cvta_generic_to_shared(s);
    asm volatile("cp.async.cg.shared.global [%0], [%1], 16;" :: "r"(sa), "l"(g));
}
#define CP_COMMIT() asm volatile("cp.async.commit_group;")
#define CP_WAIT5()  asm volatile("cp.async.wait_group 5;" ::: "memory")

// pack 4 floats -> uint2 of half2s; unpack back
__device__ __forceinline__ uint2 pack_h4(float4 e) {
    __half2 a = __floats2half2_rn(e.x, e.y);
    __half2 b = __floats2half2_rn(e.z, e.w);
    uint2 r;
    r.x = *reinterpret_cast<unsigned*>(&a);
    r.y = *reinterpret_cast<unsigned*>(&b);
    return r;
}
__device__ __forceinline__ float4 unpack_h4(uint2 h) {
    __half2 a = *reinterpret_cast<__half2*>(&h.x);
    __half2 b = *reinterpret_cast<__half2*>(&h.y);
    float2 f0 = __half22float2(a);
    float2 f1 = __half22float2(b);
    return make_float4(f0.x, f0.y, f1.x, f1.y);
}

// ---------------------------------------------------------------------------
// k1: persistent blocks. bufP (fp32, 6 chunks) recycled in-flight via
// cp.async with 1 commit group per chunk. bufE holds row r-1 exps in HALF
// precision (deferred normalize) -> smem traffic 320B/thread/row < DRAM
// fair-share, making DRAM the sole binder.
// ---------------------------------------------------------------------------
__global__ __launch_bounds__(NT, 1) void k1_main(const float* __restrict__ logits,
                                                 const int* __restrict__ targets,
                                                 int ngrid) {
    extern __shared__ float4 smem[];
    float4* bufP = smem;                                   // 6144 float4 = 96 KB
    uint2*  bufE = reinterpret_cast<uint2*>(smem + NPF * NT); // 8000 uint2 = 62.5 KB
    __shared__ float redm[32], redz[32];
    __shared__ float s_z, s_lt;

    const int tid  = threadIdx.x;
    const int lane = tid & 31;
    const int wid  = tid >> 5;
    const bool has7 = (tid + 7 * NT) < NV4;   // k=7 partial (tid < 832)

    float4 acc[8];
#pragma unroll
    for (int k = 0; k < 8; k++) acc[k] = make_float4(0.f, 0.f, 0.f, 0.f);

    // zero own bufE slots (first-row acc uses invZp=0; avoid NaN*0 from stale smem)
#pragma unroll
    for (int k = 0; k < 7; k++) bufE[tid + k * NT] = make_uint2(0u, 0u);
    if (has7) bufE[tid + 7 * NT] = make_uint2(0u, 0u);

    // prologue: prefetch first row, one commit group per chunk (NPF groups)
    const float4* r0 = reinterpret_cast<const float4*>(logits + (size_t)blockIdx.x * CC);
#pragma unroll
    for (int k = 0; k < NPF; k++) {
        cp16(bufP + tid + k * NT, r0 + tid + k * NT);
        CP_COMMIT();
    }
    float4 v6 = __ldcs(r0 + tid + 6 * NT);
    float4 v7 = has7 ? __ldcs(r0 + tid + 7 * NT) : make_float4(0.f, 0.f, 0.f, 0.f);

    float local_cls = 0.0f;
    float invZp = 0.0f;

    for (int row = blockIdx.x; row < BB; row += ngrid) {
        const int next = row + ngrid;
        const bool hasNext = next < BB;
        const float4* rn = reinterpret_cast<const float4*>(logits + (size_t)next * CC);
        const int tgt  = __ldg(targets + row);
        const int tgt4 = tgt >> 2, tgtc = tgt & 3;

        float m_t = -1e30f;
        float z_t = 0.0f;

#pragma unroll
        for (int k = 0; k < NPF; k++) {
            const int j = tid + k * NT;
            CP_WAIT5();                       // group for this chunk retired
            float4 v = bufP[j];
            if (hasNext) cp16(bufP + j, rn + j);   // recycle slot immediately
            CP_COMMIT();                      // unconditional: uniform group count
            float4 eo = unpack_h4(bufE[j]);
            acc[k].x = fmaf(eo.x, invZp, acc[k].x);
            acc[k].y = fmaf(eo.y, invZp, acc[k].y);
            acc[k].z = fmaf(eo.z, invZp, acc[k].z);
            acc[k].w = fmaf(eo.w, invZp, acc[k].w);
            float4 e;
            e.x = __expf(v.x); e.y = __expf(v.y);
            e.z = __expf(v.z); e.w = __expf(v.w);
            bufE[j] = pack_h4(e);
            m_t = fmaxf(m_t, fmaxf(fmaxf(v.x, v.y), fmaxf(v.z, v.w)));
            z_t += (e.x + e.y) + (e.z + e.w);
            if (j == tgt4) {
                s_lt = (tgtc == 0) ? v.x : ((tgtc == 1) ? v.y : ((tgtc == 2) ? v.z : v.w));
                if (tgtc == 0) acc[k].x -= 1.0f;
                else if (tgtc == 1) acc[k].y -= 1.0f;
                else if (tgtc == 2) acc[k].z -= 1.0f;
                else acc[k].w -= 1.0f;
            }
        }
        // chunks 6, 7 from registers
#pragma unroll
        for (int k = 6; k < 8; k++) {
            if (k == 7 && !has7) break;
            const int j = tid + k * NT;
            float4 v = (k == 6) ? v6 : v7;
            float4 eo = unpack_h4(bufE[j]);
            acc[k].x = fmaf(eo.x, invZp, acc[k].x);
            acc[k].y = fmaf(eo.y, invZp, acc[k].y);
            acc[k].z = fmaf(eo.z, invZp, acc[k].z);
            acc[k].w = fmaf(eo.w, invZp, acc[k].w);
            float4 e;
            e.x = __expf(v.x); e.y = __expf(v.y);
            e.z = __expf(v.z); e.w = __expf(v.w);
            bufE[j] = pack_h4(e);
            m_t = fmaxf(m_t, fmaxf(fmaxf(v.x, v.y), fmaxf(v.z, v.w)));
            z_t += (e.x + e.y) + (e.z + e.w);
            if (j == tgt4) {
                s_lt = (tgtc == 0) ? v.x : ((tgtc == 1) ? v.y : ((tgtc == 2) ? v.z : v.w));
                if (tgtc == 0) acc[k].x -= 1.0f;
                else if (tgtc == 1) acc[k].y -= 1.0f;
                else if (tgtc == 2) acc[k].z -= 1.0f;
                else acc[k].w -= 1.0f;
            }
        }
        // next-row register chunks: stream under the reduce
        if (hasNext) {
            v6 = __ldcs(rn + tid + 6 * NT);
            if (has7) v7 = __ldcs(rn + tid + 7 * NT);
        }

        // joint (max, sum) block reduce; scalar epilogue in the barrier window
        float m = warp_max(m_t);
        float z = warp_sum(z_t);
        if (lane == 0) { redm[wid] = m; redz[wid] = z; }
        __syncthreads();
        if (wid == 0) {
            m = warp_max(redm[lane]);
            z = warp_sum(redz[lane]);
            if (lane == 0) {
                s_z = z;
                float iz = 1.0f / z;
                g_conf[row] = __expf(m) * iz;     // max softmax prob
                local_cls += (logf(z) - s_lt);    // -log p[target], s_lt safe here
            }
        }
        __syncthreads();
        invZp = 1.0f / s_z;
    }

    // epilogue: pass-3 for the last processed row
#pragma unroll
    for (int k = 0; k < 8; k++) {
        if (k == 7 && !has7) break;
        float4 e = unpack_h4(bufE[tid + k * NT]);
        acc[k].x = fmaf(e.x, invZp, acc[k].x);
        acc[k].y = fmaf(e.y, invZp, acc[k].y);
        acc[k].z = fmaf(e.z, invZp, acc[k].z);
        acc[k].w = fmaf(e.w, invZp, acc[k].w);
    }

    // flush per-block column partials (coalesced float4 stores; stay in L2 for k2)
    float4* pp = reinterpret_cast<float4*>(g_partial) + (size_t)blockIdx.x * NV4;
#pragma unroll
    for (int k = 0; k < 7; k++) pp[tid + k * NT] = acc[k];
    if (has7) pp[tid + 7 * NT] = acc[7];
    if (tid == 0) g_cls_arr[blockIdx.x] = local_cls;
}

// ---------------------------------------------------------------------------
// k2: blocks 0..124 -> MDCA column reduce; blocks 125..128 -> CRL ranking.
// Last block (ticket) also does the final combine (fused former k3).
// ---------------------------------------------------------------------------
__global__ void k2_reduce(int ngrid, const int* __restrict__ idx,
                          const float* __restrict__ corr,
                          float* __restrict__ out) {
    __shared__ float red[32];
    __shared__ int s_last;
    const int tid = threadIdx.x, lane = tid & 31, wid = tid >> 5;
    const int bid = blockIdx.x;
    float s = 0.0f;

    if (bid < NCALB) {
        int c = bid * 256 + tid;
        float cs = 0.0f;
        for (int b = 0; b < ngrid; b++) cs += g_partial[(size_t)b * CC + c];
        s = fabsf(cs);                            // |colsum(p) - count|
    } else {
        int base = (bid - NCALB) * 1024;
        for (int t = tid; t < 1024; t += 256) {
            int b  = base + t;
            int b2 = (b + 1) & (BB - 1);
            float conf1 = g_conf[b];
            float conf2 = g_conf[b2];
            float c1 = __ldg(corr + __ldg(idx + b));
            float c2 = __ldg(corr + __ldg(idx + b2));
            float d  = c1 - c2;
            float rt = (d > 0.f) ? 1.f : ((d < 0.f) ? -1.f : 0.f);
            float tnz = (rt == 0.f) ? 1.f : rt;
            float ri2 = conf2 + fabsf(d) * tnz;   // margin/tnz == margin*tnz
            s += fmaxf(0.f, -rt * (conf1 - ri2));
        }
    }

    s = warp_sum(s);
    if (lane == 0) red[wid] = s;
    __syncthreads();
    if (tid == 0) {
        s = 0.0f;
#pragma unroll
        for (int w = 0; w < 8; w++) s += red[w];
        if (bid < NCALB) g_cal_arr[bid] = s;
        else             g_crl_arr[bid - NCALB] = s;
        __threadfence();
        unsigned t = atomicAdd(&g_ticket, 1u);
        s_last = (t == (unsigned)(NCALB + NCRLB - 1));
        if (s_last) g_ticket = 0;                 // self-reset for graph replay
    }
    __syncthreads();

    if (s_last) {
        __threadfence();                          // acquire published partials
        float cal = 0.f, cls = 0.f, crl = 0.f;
        for (int i = tid; i < NCALB; i += 256) cal += g_cal_arr[i];
        for (int i = tid; i < ngrid; i += 256) cls += g_cls_arr[i];
        if (tid < NCRLB) crl = g_crl_arr[tid];
        float tot = cls * (1.0f / BB) + crl * (1.0f / BB)
                  + cal * (1.0f / ((float)BB * (float)CC));
        tot = warp_sum(tot);
        if (lane == 0) red[wid] = tot;
        __syncthreads();
        if (wid == 0) {
            tot = (lane < 8) ? red[lane] : 0.0f;
            tot = warp_sum(tot);
            if (lane == 0) out[0] = tot;
        }
    }
}

extern "C" void kernel_launch(void* const* d_in, const int* in_sizes, int n_in,
                              void* d_out, int out_size) {
    const float* logits  = (const float*)d_in[0];
    const int*   targets = (const int*)d_in[1];
    const int*   idx     = (const int*)d_in[2];
    const float* corr    = (const float*)d_in[3];
    float* out = (float*)d_out;

    int sm = 148;
    cudaDeviceGetAttribute(&sm, cudaDevAttrMultiProcessorCount, 0);
    int ngrid = sm < MAXGRID ? sm : MAXGRID;

    const int smem_bytes = NPF * NT * (int)sizeof(float4)   // bufP 98304
                         + NV4 * (int)sizeof(uint2);        // bufE 64000
    cudaFuncSetAttribute(k1_main, cudaFuncAttributeMaxDynamicSharedMemorySize,
                         smem_bytes);

    k1_main<<<ngrid, NT, smem_bytes>>>(logits, targets, ngrid);
    k2_reduce<<<NCALB + NCRLB, 256>>>(ngrid, idx, corr, out);
}